// round 15
// baseline (speedup 1.0000x reference)
#include <cuda_runtime.h>
#include <math.h>
#include <stdint.h>

#define NN    8192
#define DINN  256
#define DOUTT 128
#define LALPHA 0.2f
#define MAXK  128
#define RPB   2          // rows per block in k_row

// ---------------- scratch (no allocation allowed) ----------------
__device__ __align__(16) float g_h[NN * DOUTT];     // h = input @ W
__device__ __align__(16) float g_s[NN];             // h @ a_self
__device__ __align__(16) float g_t[NN];             // h @ a_neighs
__device__ __align__(16) float g_E[2 * NN];         // interleaved {E1=e^t, E2=e^(0.2t)}
__device__ __align__(16) float g_tsorted[NN];       // t sorted descending
__device__ __align__(16) int   g_perm[NN];          // perm[rank] = j

// ---------------- packed fp32x2 helpers ----------------
__device__ __forceinline__ unsigned long long pack2(float lo, float hi) {
    unsigned long long r;
    asm("mov.b64 %0, {%1, %2};" : "=l"(r) : "r"(__float_as_uint(lo)), "r"(__float_as_uint(hi)));
    return r;
}
__device__ __forceinline__ void unpack2(unsigned long long v, float& lo, float& hi) {
    unsigned a, b;
    asm("mov.b64 {%0, %1}, %2;" : "=r"(a), "=r"(b) : "l"(v));
    lo = __uint_as_float(a); hi = __uint_as_float(b);
}
__device__ __forceinline__ unsigned long long ffma2(unsigned long long a, unsigned long long b,
                                                    unsigned long long c) {
    unsigned long long d;
    asm("fma.rn.f32x2 %0, %1, %2, %3;" : "=l"(d) : "l"(a), "l"(b), "l"(c));
    return d;
}
// max(e.lo*ab.lo, e.hi*ab.hi)  == exp(leaky(s+t)) identity (exp monotone)
__device__ __forceinline__ float max2(unsigned long long e, unsigned long long ab) {
    unsigned long long p;
    asm("mul.rn.f32x2 %0, %1, %2;" : "=l"(p) : "l"(e), "l"(ab));
    float lo, hi; unpack2(p, lo, hi);
    return fmaxf(lo, hi);
}

__device__ __forceinline__ void cp16(uint32_t dst, const void* src) {
    asm volatile("cp.async.cg.shared.global [%0], [%1], 16;" :: "r"(dst), "l"(src));
}
__device__ __forceinline__ uint32_t sptr(const void* p) {
    return (uint32_t)__cvta_generic_to_shared(p);
}

// ---------------- h = input @ W  (M=8192, K=256, N=128) + fused stats ----------------
// M-tile 64, 8 rows/warp (2x B-reuse vs R6), K-chunk 32, 2-stage cp.async. smem 48KB.
__global__ __launch_bounds__(256) void k_gemm(const float* __restrict__ X,
                                              const float* __restrict__ W,
                                              const float* __restrict__ a_self,
                                              const float* __restrict__ a_neighs) {
    __shared__ float As[2][64][32];     // 16 KB
    __shared__ float Bs[2][32][128];    // 32 KB
    int tid  = threadIdx.x;
    int m0   = blockIdx.x * 64;
    int warp = tid >> 5;
    int lane = tid & 31;

    auto issue = [&](int s) {
        int k0 = s * 32, buf = s & 1;
#pragma unroll
        for (int l = 0; l < 2; l++) {                // A: 512 float4
            int idx = l * 256 + tid;
            int ar = idx >> 3, ak = (idx & 7) * 4;
            cp16(sptr(&As[buf][ar][ak]), X + (size_t)(m0 + ar) * DINN + k0 + ak);
        }
#pragma unroll
        for (int l = 0; l < 4; l++) {                // B: 1024 float4
            int idx = l * 256 + tid;
            int kk = idx >> 5, n4 = (idx & 31) * 4;
            cp16(sptr(&Bs[buf][kk][n4]), W + (size_t)(k0 + kk) * DOUTT + n4);
        }
        asm volatile("cp.async.commit_group;");
    };

    unsigned long long acc01[8], acc23[8];
#pragma unroll
    for (int r = 0; r < 8; r++) { acc01[r] = 0ull; acc23[r] = 0ull; }

    issue(0);
    issue(1);

#pragma unroll
    for (int s = 0; s < 8; s++) {
        if (s + 2 < 8) { asm volatile("cp.async.wait_group 1;"); }
        else           { asm volatile("cp.async.wait_group 0;"); }
        __syncthreads();
        int buf = s & 1;
#pragma unroll
        for (int kk4 = 0; kk4 < 8; ++kk4) {
            float4 a4[8];
#pragma unroll
            for (int r = 0; r < 8; r++)
                a4[r] = *(const float4*)&As[buf][warp * 8 + r][kk4 * 4];
#pragma unroll
            for (int e = 0; e < 4; e++) {
                float4 b = *(const float4*)&Bs[buf][kk4 * 4 + e][lane * 4];
                unsigned long long b01 = pack2(b.x, b.y);
                unsigned long long b23 = pack2(b.z, b.w);
#pragma unroll
                for (int r = 0; r < 8; r++) {
                    float a = (e == 0) ? a4[r].x : (e == 1) ? a4[r].y : (e == 2) ? a4[r].z : a4[r].w;
                    unsigned long long aa = pack2(a, a);
                    acc01[r] = ffma2(aa, b01, acc01[r]);
                    acc23[r] = ffma2(aa, b23, acc23[r]);
                }
            }
        }
        __syncthreads();
        if (s + 2 < 8) issue(s + 2);
    }

    // epilogue: store h + fused per-row stats (s, t, E1, E2)
    float4 as4 = ((const float4*)a_self)[lane];
    float4 an4 = ((const float4*)a_neighs)[lane];
#pragma unroll
    for (int r = 0; r < 8; r++) {
        float4 v;
        unpack2(acc01[r], v.x, v.y);
        unpack2(acc23[r], v.z, v.w);
        int row = m0 + warp * 8 + r;
        *(float4*)(g_h + (size_t)row * DOUTT + lane * 4) = v;

        float s = v.x * as4.x + v.y * as4.y + v.z * as4.z + v.w * as4.w;
        float t = v.x * an4.x + v.y * an4.y + v.z * an4.z + v.w * an4.w;
#pragma unroll
        for (int o = 16; o; o >>= 1) {
            s += __shfl_xor_sync(0xffffffffu, s, o);
            t += __shfl_xor_sync(0xffffffffu, t, o);
        }
        if (lane == 0) {
            g_s[row] = s;
            g_t[row] = t;
            g_E[2 * row]     = __expf(t);
            g_E[2 * row + 1] = __expf(LALPHA * t);
        }
    }
}

// ---------------- global descending rank sort of t (stable, exact) ----------------
__global__ __launch_bounds__(256) void k_rank() {
    __shared__ float ts[NN];        // 32 KB
    __shared__ int   partial[256];
    int tid = threadIdx.x;
#pragma unroll
    for (int l = 0; l < 8; l++) {
        int lin = l * 1024 + tid * 4;
        *(float4*)&ts[lin] = *(const float4*)(g_t + lin);
    }
    __syncthreads();

    int local = tid >> 2;
    int q     = tid & 3;              // interleaved quarters -> conflict-free float4s
    int j     = blockIdx.x * 64 + local;
    float tj  = ts[j];
    int cnt = 0;
#pragma unroll 4
    for (int k4 = 0; k4 < 512; ++k4) {
        int fidx = k4 * 4 + q;
        float4 v = *(const float4*)&ts[fidx * 4];
        int k = fidx * 4;
        cnt += (v.x > tj) || (v.x == tj && k     < j);
        cnt += (v.y > tj) || (v.y == tj && k + 1 < j);
        cnt += (v.z > tj) || (v.z == tj && k + 2 < j);
        cnt += (v.w > tj) || (v.w == tj && k + 3 < j);
    }
    partial[tid] = cnt;
    __syncthreads();
    if (q == 0) {
        int rank = partial[tid] + partial[tid + 1] + partial[tid + 2] + partial[tid + 3];
        g_perm[rank]    = j;
        g_tsorted[rank] = tj;
    }
}

// adj-bit test: word ((j>>10)<<8) + ((j>>2)&255); row0 bit (j&3), row1 bit 4+(j&3)
#define BITTEST(r, j) \
    ((s_nibw[(((j) >> 10) << 8) + (((j) >> 2) & 255)] >> ((r) * 4 + ((j) & 3))) & 1)

// ---------------- main fused row kernel (R13 best: direct LDG, cap 6) ----------------
__global__ __launch_bounds__(256, 6) void k_row(const int* __restrict__ adj,
                                                const int* __restrict__ action,
                                                const int* __restrict__ bp,
                                                float* __restrict__ out) {
    __shared__ unsigned s_nibw[2048];              // 8 bits used/word, conflict-free (8 KB)
    __shared__ float s_red[RPB][8];
    __shared__ float s_par[RPB][3];                // A, B, denom
    __shared__ int   s_info[RPB][2];               // kept count, fallback flag
    __shared__ int   s_klist[RPB][MAXK];
    __shared__ float s_wlist[RPB][MAXK];

    int tid  = threadIdx.x;
    int lane = tid & 31, warp = tid >> 5;
    int row0 = blockIdx.x * RPB;

    unsigned long long AB0, AB1;
    {
        float s0 = g_s[row0], s1 = g_s[row0 + 1];
        AB0 = pack2(__expf(s0), __expf(LALPHA * s0));
        AB1 = pack2(__expf(s1), __expf(LALPHA * s1));
    }
    const int* ap = adj + (size_t)row0 * NN;       // row1 = ap + NN

    float acc0a = 0.f, acc0b = 0.f, acc1a = 0.f, acc1b = 0.f;
#pragma unroll
    for (int it = 0; it < 8; ++it) {
        int base = it * 1024 + tid * 4;
        int4 a0 = __ldcs((const int4*)(ap + base));
        int4 a1 = __ldcs((const int4*)(ap + NN + base));
        float4 eA = __ldg((const float4*)(g_E + 2 * base));       // {E1,E2} of j0,j1
        float4 eB = __ldg((const float4*)(g_E + 2 * base + 4));   // {E1,E2} of j2,j3
        unsigned long long e0 = pack2(eA.x, eA.y);
        unsigned long long e1 = pack2(eA.z, eA.w);
        unsigned long long e2 = pack2(eB.x, eB.y);
        unsigned long long e3 = pack2(eB.z, eB.w);

        // masks are the 0/1 values themselves
        acc0a = fmaf((float)a0.x, max2(e0, AB0), acc0a);
        acc0b = fmaf((float)a0.y, max2(e1, AB0), acc0b);
        acc0a = fmaf((float)a0.z, max2(e2, AB0), acc0a);
        acc0b = fmaf((float)a0.w, max2(e3, AB0), acc0b);
        acc1a = fmaf((float)a1.x, max2(e0, AB1), acc1a);
        acc1b = fmaf((float)a1.y, max2(e1, AB1), acc1b);
        acc1a = fmaf((float)a1.z, max2(e2, AB1), acc1a);
        acc1b = fmaf((float)a1.w, max2(e3, AB1), acc1b);

        // bitmap word from 0/1 ints (IMAD chain, no compares)
        unsigned nb0 = (unsigned)(a0.x + a0.y * 2 + a0.z * 4 + a0.w * 8);
        unsigned nb1 = (unsigned)(a1.x + a1.y * 2 + a1.z * 4 + a1.w * 8);
        s_nibw[it * 256 + tid] = nb0 | (nb1 << 4);
    }
    float acc0 = acc0a + acc0b;
    float acc1 = acc1a + acc1b;
#pragma unroll
    for (int o = 16; o; o >>= 1) {
        acc0 += __shfl_xor_sync(0xffffffffu, acc0, o);
        acc1 += __shfl_xor_sync(0xffffffffu, acc1, o);
    }
    if (lane == 0) { s_red[0][warp] = acc0; s_red[1][warp] = acc1; }
    __syncthreads();

    if (warp < RPB) {                // warps 0,1 each own one row
        int r = warp;
        int row = row0 + r;
        unsigned long long ABr = r ? AB1 : AB0;
        float A, B;
        unpack2(ABr, A, B);

        float S = (lane < 8) ? s_red[r][lane] : 0.f;
#pragma unroll
        for (int o = 4; o; o >>= 1)
            S += __shfl_xor_sync(0xffffffffu, S, o);
        float denom = __shfl_sync(0xffffffffu, S, 0);
        if (lane == 0) { s_par[r][0] = A; s_par[r][1] = B; s_par[r][2] = denom; }

        int fallback = 0;
        int c2 = 0;
        if (__ldg(bp) != 0) {
            int target = __ldg(action + row) + 1;   // keep `target` entries (+ exact ties)
            // Phase A: threshold = target-th largest valid t (sorted walk + bitmap)
            int cnt = 0, pos = 0, found = 0;
            float t_thr = 0.f;
            while (pos < NN) {
                int ridx = pos + lane;
                int j = g_perm[ridx];
                float tv = g_tsorted[ridx];
                int bit = BITTEST(r, j);
                unsigned bal = __ballot_sync(0xffffffffu, bit);
                int c = __popc(bal);
                if (cnt + c >= target) {
                    int prefx = __popc(bal & ((1u << lane) - 1));
                    int sel = bit && (cnt + prefx + 1 == target);
                    unsigned sm = __ballot_sync(0xffffffffu, sel);
                    int src = __ffs(sm) - 1;
                    t_thr = __shfl_sync(0xffffffffu, tv, src);
                    found = 1;
                    break;
                }
                cnt += c;
                pos += 32;
            }
            if (!found) fallback = 1;   // fewer valid than target -> threshold 0 -> keep all

            // Phase B: collect kept (valid & t >= t_thr) with normalized weights
            if (!fallback) {
                pos = 0;
                while (pos < NN) {
                    int ridx = pos + lane;
                    float tv = g_tsorted[ridx];
                    int j = g_perm[ridx];
                    int bit = BITTEST(r, j);
                    bool ge = (tv >= t_thr);
                    bool keep = bit && ge;
                    unsigned balk = __ballot_sync(0xffffffffu, keep);
                    int idx = c2 + __popc(balk & ((1u << lane) - 1));
                    if (keep && idx < MAXK) {
                        unsigned long long ep = pack2(__ldg(&g_E[2 * j]), __ldg(&g_E[2 * j + 1]));
                        s_klist[r][idx] = j;
                        s_wlist[r][idx] = max2(ep, ABr) / denom;
                    }
                    c2 += __popc(balk);
                    if (c2 > MAXK) break;                                      // tie explosion
                    if (__ballot_sync(0xffffffffu, ge) != 0xffffffffu) break;  // sorted: done
                    pos += 32;
                }
                if (c2 > MAXK) fallback = 1;
            }
        } else {
            fallback = 1;   // no thresholding: dense path over all valid
        }
        if (lane == 0) { s_info[r][0] = c2; s_info[r][1] = fallback; }
    }
    __syncthreads();

    // epilogue: one (row, dim) per thread
    int r = tid >> 7, d = tid & 127;
    int row = row0 + r;
    int c2 = s_info[r][0];
    int fb = s_info[r][1];
    float a = 0.f;
    if (!fb) {
#pragma unroll 4
        for (int k = 0; k < c2; ++k)
            a += s_wlist[r][k] * g_h[(size_t)s_klist[r][k] * DOUTT + d];
    } else {
        unsigned long long ABr = pack2(s_par[r][0], s_par[r][1]);
        float inv = 1.f / s_par[r][2];
        for (int j = 0; j < NN; ++j) {
            if (BITTEST(r, j)) {
                unsigned long long ep = pack2(__ldg(&g_E[2 * j]), __ldg(&g_E[2 * j + 1]));
                a += max2(ep, ABr) * inv * g_h[(size_t)j * DOUTT + d];
            }
        }
    }
    out[(size_t)row * DOUTT + d] = (a > 0.f) ? a : expm1f(a);
}

// ---------------- launch ----------------
extern "C" void kernel_launch(void* const* d_in, const int* in_sizes, int n_in,
                              void* d_out, int out_size) {
    const float* input    = (const float*)d_in[0];
    const int*   adj      = (const int*)d_in[1];
    const int*   action   = (const int*)d_in[2];
    const float* W        = (const float*)d_in[3];
    const float* a_self   = (const float*)d_in[4];
    const float* a_neighs = (const float*)d_in[5];
    const int*   bp       = (const int*)d_in[6];
    float* out = (float*)d_out;

    k_gemm<<<NN / 64, 256>>>(input, W, a_self, a_neighs);
    k_rank<<<NN / 64, 256>>>();
    k_row<<<NN / RPB, 256>>>(adj, action, bp, out);
}

// round 16
// speedup vs baseline: 1.3404x; 1.3404x over previous
#include <cuda_runtime.h>
#include <math.h>
#include <stdint.h>

#define NN    8192
#define DINN  256
#define DOUTT 128
#define LALPHA 0.2f
#define MAXK  128
#define RPB   2          // rows per block in k_row

// ---------------- scratch (no allocation allowed) ----------------
__device__ __align__(16) float g_h[NN * DOUTT];     // h = input @ W
__device__ __align__(16) float g_s[NN];             // h @ a_self
__device__ __align__(16) float g_t[NN];             // h @ a_neighs
__device__ __align__(16) float g_E2[NN];            // e^(0.2*t)  (E1 = E2^5)
__device__ __align__(16) float g_tsorted[NN];       // t sorted descending
__device__ __align__(16) int   g_perm[NN];          // perm[rank] = j

// ---------------- packed fp32x2 helpers (gemm only) ----------------
__device__ __forceinline__ unsigned long long pack2(float lo, float hi) {
    unsigned long long r;
    asm("mov.b64 %0, {%1, %2};" : "=l"(r) : "r"(__float_as_uint(lo)), "r"(__float_as_uint(hi)));
    return r;
}
__device__ __forceinline__ void unpack2(unsigned long long v, float& lo, float& hi) {
    unsigned a, b;
    asm("mov.b64 {%0, %1}, %2;" : "=r"(a), "=r"(b) : "l"(v));
    lo = __uint_as_float(a); hi = __uint_as_float(b);
}
__device__ __forceinline__ unsigned long long ffma2(unsigned long long a, unsigned long long b,
                                                    unsigned long long c) {
    unsigned long long d;
    asm("fma.rn.f32x2 %0, %1, %2, %3;" : "=l"(d) : "l"(a), "l"(b), "l"(c));
    return d;
}

// E1 from E2: E2^5, 3 FMULs, well-conditioned
__device__ __forceinline__ float pow5(float x) {
    float x2 = x * x;
    float x4 = x2 * x2;
    return x4 * x;
}
// zero-or-keep via integer mask (a in {0,1}): IADD3+LOP3, no I2F
__device__ __forceinline__ float maskf(float v, int a) {
    return __int_as_float(__float_as_int(v) & (-a));
}

__device__ __forceinline__ void cp16(uint32_t dst, const void* src) {
    asm volatile("cp.async.cg.shared.global [%0], [%1], 16;" :: "r"(dst), "l"(src));
}
__device__ __forceinline__ uint32_t sptr(const void* p) {
    return (uint32_t)__cvta_generic_to_shared(p);
}

// ---------------- h = input @ W  (M=8192, K=256, N=128) + fused stats ----------------
// R6 config (best measured 18.8us): M-tile 32, K-chunk 32, 2-stage cp.async.
__global__ __launch_bounds__(256) void k_gemm(const float* __restrict__ X,
                                              const float* __restrict__ W,
                                              const float* __restrict__ a_self,
                                              const float* __restrict__ a_neighs) {
    __shared__ float As[2][32][32];     // 8 KB
    __shared__ float Bs[2][32][128];    // 32 KB
    int tid  = threadIdx.x;
    int m0   = blockIdx.x * 32;
    int warp = tid >> 5;
    int lane = tid & 31;

    int ar = tid >> 3, ak = (tid & 7) * 4;          // A: 1 float4/thread/stage

    auto issue = [&](int s) {
        int k0 = s * 32, buf = s & 1;
        cp16(sptr(&As[buf][ar][ak]), X + (size_t)(m0 + ar) * DINN + k0 + ak);
#pragma unroll
        for (int l = 0; l < 4; l++) {                // B: 4 float4/thread/stage
            int idx = l * 256 + tid;
            int kk = idx >> 5, n4 = (idx & 31) * 4;
            cp16(sptr(&Bs[buf][kk][n4]), W + (size_t)(k0 + kk) * DOUTT + n4);
        }
        asm volatile("cp.async.commit_group;");
    };

    unsigned long long acc01[4], acc23[4];
#pragma unroll
    for (int r = 0; r < 4; r++) { acc01[r] = 0ull; acc23[r] = 0ull; }

    issue(0);
    issue(1);

#pragma unroll
    for (int s = 0; s < 8; s++) {
        if (s + 2 < 8) { asm volatile("cp.async.wait_group 1;"); }
        else           { asm volatile("cp.async.wait_group 0;"); }
        __syncthreads();
        int buf = s & 1;
#pragma unroll
        for (int kk4 = 0; kk4 < 8; ++kk4) {
            float4 a4[4];
#pragma unroll
            for (int r = 0; r < 4; r++)
                a4[r] = *(const float4*)&As[buf][warp * 4 + r][kk4 * 4];
#pragma unroll
            for (int e = 0; e < 4; e++) {
                float4 b = *(const float4*)&Bs[buf][kk4 * 4 + e][lane * 4];
                unsigned long long b01 = pack2(b.x, b.y);
                unsigned long long b23 = pack2(b.z, b.w);
#pragma unroll
                for (int r = 0; r < 4; r++) {
                    float a = (e == 0) ? a4[r].x : (e == 1) ? a4[r].y : (e == 2) ? a4[r].z : a4[r].w;
                    unsigned long long aa = pack2(a, a);
                    acc01[r] = ffma2(aa, b01, acc01[r]);
                    acc23[r] = ffma2(aa, b23, acc23[r]);
                }
            }
        }
        __syncthreads();
        if (s + 2 < 8) issue(s + 2);
    }

    // epilogue: store h + fused per-row stats (s, t, E2)
    float4 as4 = ((const float4*)a_self)[lane];
    float4 an4 = ((const float4*)a_neighs)[lane];
#pragma unroll
    for (int r = 0; r < 4; r++) {
        float4 v;
        unpack2(acc01[r], v.x, v.y);
        unpack2(acc23[r], v.z, v.w);
        int row = m0 + warp * 4 + r;
        *(float4*)(g_h + (size_t)row * DOUTT + lane * 4) = v;

        float s = v.x * as4.x + v.y * as4.y + v.z * as4.z + v.w * as4.w;
        float t = v.x * an4.x + v.y * an4.y + v.z * an4.z + v.w * an4.w;
#pragma unroll
        for (int o = 16; o; o >>= 1) {
            s += __shfl_xor_sync(0xffffffffu, s, o);
            t += __shfl_xor_sync(0xffffffffu, t, o);
        }
        if (lane == 0) {
            g_s[row] = s;
            g_t[row] = t;
            g_E2[row] = __expf(LALPHA * t);
        }
    }
}

// ---------------- global descending rank sort of t (stable, exact) ----------------
__global__ __launch_bounds__(256) void k_rank() {
    __shared__ float ts[NN];        // 32 KB
    __shared__ int   partial[256];
    int tid = threadIdx.x;
#pragma unroll
    for (int l = 0; l < 8; l++) {
        int lin = l * 1024 + tid * 4;
        *(float4*)&ts[lin] = *(const float4*)(g_t + lin);
    }
    __syncthreads();

    int local = tid >> 2;
    int q     = tid & 3;              // interleaved quarters -> conflict-free float4s
    int j     = blockIdx.x * 64 + local;
    float tj  = ts[j];
    int cnt = 0;
#pragma unroll 4
    for (int k4 = 0; k4 < 512; ++k4) {
        int fidx = k4 * 4 + q;
        float4 v = *(const float4*)&ts[fidx * 4];
        int k = fidx * 4;
        cnt += (v.x > tj) || (v.x == tj && k     < j);
        cnt += (v.y > tj) || (v.y == tj && k + 1 < j);
        cnt += (v.z > tj) || (v.z == tj && k + 2 < j);
        cnt += (v.w > tj) || (v.w == tj && k + 3 < j);
    }
    partial[tid] = cnt;
    __syncthreads();
    if (q == 0) {
        int rank = partial[tid] + partial[tid + 1] + partial[tid + 2] + partial[tid + 3];
        g_perm[rank]    = j;
        g_tsorted[rank] = tj;
    }
}

// adj-bit test: word ((j>>10)<<8) + ((j>>2)&255); row0 bit (j&3), row1 bit 4+(j&3)
#define BITTEST(r, j) \
    ((s_nibw[(((j) >> 10) << 8) + (((j) >> 2) & 255)] >> ((r) * 4 + ((j) & 3))) & 1)

// ---------------- main fused row kernel: E2-only loads + integer masking ----------------
// exp(leaky(s+t)) == max(A*E1, B*E2), E1 = E2^5 (3 FMULs), A=e^s, B=e^{0.2s}.
// 3 LDG.128/thread-iter instead of 4; masking via LOP3 (no I2F).
__global__ __launch_bounds__(256, 6) void k_row(const int* __restrict__ adj,
                                                const int* __restrict__ action,
                                                const int* __restrict__ bp,
                                                float* __restrict__ out) {
    __shared__ unsigned s_nibw[2048];              // 8 bits used/word, conflict-free (8 KB)
    __shared__ float s_red[RPB][8];
    __shared__ float s_par[RPB][3];                // A, B, denom
    __shared__ int   s_info[RPB][2];               // kept count, fallback flag
    __shared__ int   s_klist[RPB][MAXK];
    __shared__ float s_wlist[RPB][MAXK];

    int tid  = threadIdx.x;
    int lane = tid & 31, warp = tid >> 5;
    int row0 = blockIdx.x * RPB;

    float A0, B0, A1, B1;
    {
        float s0 = g_s[row0], s1 = g_s[row0 + 1];
        A0 = __expf(s0); B0 = __expf(LALPHA * s0);
        A1 = __expf(s1); B1 = __expf(LALPHA * s1);
    }
    const int* ap = adj + (size_t)row0 * NN;       // row1 = ap + NN

    float acc0a = 0.f, acc0b = 0.f, acc1a = 0.f, acc1b = 0.f;
#pragma unroll
    for (int it = 0; it < 8; ++it) {
        int base = it * 1024 + tid * 4;
        int4 a0 = __ldcs((const int4*)(ap + base));
        int4 a1 = __ldcs((const int4*)(ap + NN + base));
        float4 e2v = __ldg((const float4*)(g_E2 + base));   // E2 of j0..j3

        float e1x = pow5(e2v.x), e1y = pow5(e2v.y), e1z = pow5(e2v.z), e1w = pow5(e2v.w);

        acc0a += maskf(fmaxf(A0 * e1x, B0 * e2v.x), a0.x);
        acc0b += maskf(fmaxf(A0 * e1y, B0 * e2v.y), a0.y);
        acc0a += maskf(fmaxf(A0 * e1z, B0 * e2v.z), a0.z);
        acc0b += maskf(fmaxf(A0 * e1w, B0 * e2v.w), a0.w);
        acc1a += maskf(fmaxf(A1 * e1x, B1 * e2v.x), a1.x);
        acc1b += maskf(fmaxf(A1 * e1y, B1 * e2v.y), a1.y);
        acc1a += maskf(fmaxf(A1 * e1z, B1 * e2v.z), a1.z);
        acc1b += maskf(fmaxf(A1 * e1w, B1 * e2v.w), a1.w);

        // bitmap word from 0/1 ints (IMAD chain, no compares)
        unsigned nb0 = (unsigned)(a0.x + a0.y * 2 + a0.z * 4 + a0.w * 8);
        unsigned nb1 = (unsigned)(a1.x + a1.y * 2 + a1.z * 4 + a1.w * 8);
        s_nibw[it * 256 + tid] = nb0 | (nb1 << 4);
    }
    float acc0 = acc0a + acc0b;
    float acc1 = acc1a + acc1b;
#pragma unroll
    for (int o = 16; o; o >>= 1) {
        acc0 += __shfl_xor_sync(0xffffffffu, acc0, o);
        acc1 += __shfl_xor_sync(0xffffffffu, acc1, o);
    }
    if (lane == 0) { s_red[0][warp] = acc0; s_red[1][warp] = acc1; }
    __syncthreads();

    if (warp < RPB) {                // warps 0,1 each own one row
        int r = warp;
        int row = row0 + r;
        float A = r ? A1 : A0;
        float B = r ? B1 : B0;

        float S = (lane < 8) ? s_red[r][lane] : 0.f;
#pragma unroll
        for (int o = 4; o; o >>= 1)
            S += __shfl_xor_sync(0xffffffffu, S, o);
        float denom = __shfl_sync(0xffffffffu, S, 0);
        if (lane == 0) { s_par[r][0] = A; s_par[r][1] = B; s_par[r][2] = denom; }

        int fallback = 0;
        int c2 = 0;
        if (__ldg(bp) != 0) {
            int target = __ldg(action + row) + 1;   // keep `target` entries (+ exact ties)
            // Phase A: threshold = target-th largest valid t (sorted walk + bitmap)
            int cnt = 0, pos = 0, found = 0;
            float t_thr = 0.f;
            while (pos < NN) {
                int ridx = pos + lane;
                int j = g_perm[ridx];
                float tv = g_tsorted[ridx];
                int bit = BITTEST(r, j);
                unsigned bal = __ballot_sync(0xffffffffu, bit);
                int c = __popc(bal);
                if (cnt + c >= target) {
                    int prefx = __popc(bal & ((1u << lane) - 1));
                    int sel = bit && (cnt + prefx + 1 == target);
                    unsigned sm = __ballot_sync(0xffffffffu, sel);
                    int src = __ffs(sm) - 1;
                    t_thr = __shfl_sync(0xffffffffu, tv, src);
                    found = 1;
                    break;
                }
                cnt += c;
                pos += 32;
            }
            if (!found) fallback = 1;   // fewer valid than target -> threshold 0 -> keep all

            // Phase B: collect kept (valid & t >= t_thr) with normalized weights
            if (!fallback) {
                pos = 0;
                while (pos < NN) {
                    int ridx = pos + lane;
                    float tv = g_tsorted[ridx];
                    int j = g_perm[ridx];
                    int bit = BITTEST(r, j);
                    bool ge = (tv >= t_thr);
                    bool keep = bit && ge;
                    unsigned balk = __ballot_sync(0xffffffffu, keep);
                    int idx = c2 + __popc(balk & ((1u << lane) - 1));
                    if (keep && idx < MAXK) {
                        float e2 = __ldg(&g_E2[j]);
                        float w = fmaxf(A * pow5(e2), B * e2);
                        s_klist[r][idx] = j;
                        s_wlist[r][idx] = w / denom;
                    }
                    c2 += __popc(balk);
                    if (c2 > MAXK) break;                                      // tie explosion
                    if (__ballot_sync(0xffffffffu, ge) != 0xffffffffu) break;  // sorted: done
                    pos += 32;
                }
                if (c2 > MAXK) fallback = 1;
            }
        } else {
            fallback = 1;   // no thresholding: dense path over all valid
        }
        if (lane == 0) { s_info[r][0] = c2; s_info[r][1] = fallback; }
    }
    __syncthreads();

    // epilogue: one (row, dim) per thread
    int r = tid >> 7, d = tid & 127;
    int row = row0 + r;
    int c2 = s_info[r][0];
    int fb = s_info[r][1];
    float a = 0.f;
    if (!fb) {
#pragma unroll 4
        for (int k = 0; k < c2; ++k)
            a += s_wlist[r][k] * g_h[(size_t)s_klist[r][k] * DOUTT + d];
    } else {
        float A = s_par[r][0], B = s_par[r][1];
        float inv = 1.f / s_par[r][2];
        for (int j = 0; j < NN; ++j) {
            if (BITTEST(r, j)) {
                float e2 = __ldg(&g_E2[j]);
                float w = fmaxf(A * pow5(e2), B * e2) * inv;
                a += w * g_h[(size_t)j * DOUTT + d];
            }
        }
    }
    out[(size_t)row * DOUTT + d] = (a > 0.f) ? a : expm1f(a);
}

// ---------------- launch ----------------
extern "C" void kernel_launch(void* const* d_in, const int* in_sizes, int n_in,
                              void* d_out, int out_size) {
    const float* input    = (const float*)d_in[0];
    const int*   adj      = (const int*)d_in[1];
    const int*   action   = (const int*)d_in[2];
    const float* W        = (const float*)d_in[3];
    const float* a_self   = (const float*)d_in[4];
    const float* a_neighs = (const float*)d_in[5];
    const int*   bp       = (const int*)d_in[6];
    float* out = (float*)d_out;

    k_gemm<<<NN / 32, 256>>>(input, W, a_self, a_neighs);
    k_rank<<<NN / 64, 256>>>();
    k_row<<<NN / RPB, 256>>>(adj, action, bp, out);
}